// round 12
// baseline (speedup 1.0000x reference)
#include <cuda_runtime.h>
#include <cuda_fp16.h>
#include <cstdint>

#define N_GENOMES 30000
#define N_GENES   240000
#define N_SAMPLES 128
#define N_SEQS    80000
#define CAP       32   // Poisson(3): P(any of 80K seqs > 32 genes) ~ 1e-16
#define LOG2E     1.4426950408889634f
#define ROW_BYTES (N_SAMPLES * 4)   // 512 B per genome row in d_C

#define MAIN_BLOCKS 740             // 5 CTAs/SM floor -> one resident wave
#define NWARPS      (MAIN_BLOCKS * 8)

#define CONV_VEC  ((N_GENOMES * N_SAMPLES) / 4)
#define CONV_BLK  1184
#define SCAT_BLK  ((N_GENES + 255) / 256)
#define PREP_BLK  (CONV_BLK + SCAT_BLK)

// Scratch (device globals, zero-initialized at module load).
// d_C: per-genome interleaved fp16 (a_i,b_i) -> 512 B/row, 15.4 MB, L2-resident.
__device__ __half2 d_C[(size_t)N_GENOMES * N_SAMPLES];
__device__ int     d_count[N_SEQS];
__device__ int2    d_pairs[(size_t)N_SEQS * CAP];  // {row BYTE offset, bits(-pos*log2e)}

__device__ __forceinline__ float ex2f(float x) {
    float r; asm("ex2.approx.f32 %0, %1;" : "=f"(r) : "f"(x)); return r;
}
__device__ __forceinline__ uint32_t pack2(float a, float b) {
    __half2 h = __floats2half2_rn(a, b);
    return *reinterpret_cast<uint32_t*>(&h);
}

// Fused prep: blocks [0, CONV_BLK) build the fp16 table (float4 loads, MLP 8);
// blocks [CONV_BLK, PREP_BLK) bucket genes by sequence.
__global__ void __launch_bounds__(256) prep_kernel(
    const float* __restrict__ A,
    const float* __restrict__ B,
    const float* __restrict__ pos,
    const int*   __restrict__ genome_idx,
    const int*   __restrict__ seq_idx)
{
    if (blockIdx.x < CONV_BLK) {
        const float4* A4 = reinterpret_cast<const float4*>(A);
        const float4* B4 = reinterpret_cast<const float4*>(B);
        uint4* C4 = reinterpret_cast<uint4*>(d_C);
        const int stride = CONV_BLK * 256;
        for (int i = blockIdx.x * 256 + threadIdx.x; i < CONV_VEC; i += stride) {
            const float4 a = __ldg(A4 + i);
            const float4 b = __ldg(B4 + i);
            uint4 o;
            o.x = pack2(a.x, b.x);
            o.y = pack2(a.y, b.y);
            o.z = pack2(a.z, b.z);
            o.w = pack2(a.w, b.w);
            C4[i] = o;
        }
    } else {
        const int g = (blockIdx.x - CONV_BLK) * 256 + threadIdx.x;
        if (g >= N_GENES) return;
        const int   s   = seq_idx[g];
        const int   off = genome_idx[g] * ROW_BYTES;      // premultiplied bytes
        const float np  = -pos[g] * LOG2E;
        const int slot = atomicAdd(&d_count[s], 1);
        if (slot < CAP)
            d_pairs[(size_t)s * CAP + slot] = make_int2(off, __float_as_int(np));
    }
}

// exp(A + 1 - p*B) = ex2( fma(B, -p*log2e, fma(A, log2e, log2e)) )
__device__ __forceinline__ void acc_gene(float4& acc, const uint4 v, const float np) {
    const float2 p0 = __half22float2(*reinterpret_cast<const __half2*>(&v.x));
    const float2 p1 = __half22float2(*reinterpret_cast<const __half2*>(&v.y));
    const float2 p2 = __half22float2(*reinterpret_cast<const __half2*>(&v.z));
    const float2 p3 = __half22float2(*reinterpret_cast<const __half2*>(&v.w));
    acc.x += ex2f(fmaf(p0.y, np, fmaf(p0.x, LOG2E, LOG2E)));
    acc.y += ex2f(fmaf(p1.y, np, fmaf(p1.x, LOG2E, LOG2E)));
    acc.z += ex2f(fmaf(p2.y, np, fmaf(p2.x, LOG2E, LOG2E)));
    acc.w += ex2f(fmaf(p3.y, np, fmaf(p3.x, LOG2E, LOG2E)));
}

// Main: persistent warp per seq, one resident wave, pointer-increment
// addressing (compile-time strides), 2-unrolled depth-2 gene pipeline.
// Resets d_count inline for the next graph replay.
__global__ void __launch_bounds__(256) seq_segsum_kernel(float* __restrict__ out)
{
    const int lane = threadIdx.x & 31;
    int seq = (blockIdx.x * blockDim.x + threadIdx.x) >> 5;
    const int laneB = lane * 16;

    const char* __restrict__ Cb = reinterpret_cast<const char*>(d_C);

    int*        cptr = d_count + seq;
    const int2* pptr = d_pairs + (size_t)seq * CAP + lane;
    float*      optr = out + (size_t)seq * N_SAMPLES + lane * 4;

    int  tn  = __ldg(cptr);
    int2 prn = *pptr;

    while (true) {
        const int  t  = min(tn, CAP);
        const int2 pr = prn;
        if (lane == 0) *cptr = 0;                 // reset for next replay

        seq += NWARPS;
        const bool more = (seq < N_SEQS);
        if (more) {                               // prefetch next seq metadata
            cptr += NWARPS;
            pptr += (size_t)NWARPS * CAP;
            tn  = __ldg(cptr);
            prn = *pptr;
        }

        float4 acc = make_float4(0.f, 0.f, 0.f, 0.f);
        if (t > 0) {
            int   o0 = __shfl_sync(0xffffffffu, pr.x, 0) + laneB;
            float n0 = __int_as_float(__shfl_sync(0xffffffffu, pr.y, 0));
            uint4 v0 = *reinterpret_cast<const uint4*>(Cb + o0);
            if (t > 1) {
                int   o1 = __shfl_sync(0xffffffffu, pr.x, 1) + laneB;
                float n1 = __int_as_float(__shfl_sync(0xffffffffu, pr.y, 1));
                uint4 v1 = *reinterpret_cast<const uint4*>(Cb + o1);

                int k = 2;
                // 2-unrolled pipelined loop: no register rotation MOVs.
                for (; k + 2 <= t; k += 2) {
                    const int   oa = __shfl_sync(0xffffffffu, pr.x, k) + laneB;
                    const float na = __int_as_float(__shfl_sync(0xffffffffu, pr.y, k));
                    const uint4 va = *reinterpret_cast<const uint4*>(Cb + oa);
                    acc_gene(acc, v0, n0);
                    const int   ob = __shfl_sync(0xffffffffu, pr.x, k + 1) + laneB;
                    const float nb = __int_as_float(__shfl_sync(0xffffffffu, pr.y, k + 1));
                    const uint4 vb = *reinterpret_cast<const uint4*>(Cb + ob);
                    acc_gene(acc, v1, n1);
                    v0 = va; n0 = na;
                    v1 = vb; n1 = nb;
                }
                if (k < t) {                       // one leftover gene
                    const int   oa = __shfl_sync(0xffffffffu, pr.x, k) + laneB;
                    const float na = __int_as_float(__shfl_sync(0xffffffffu, pr.y, k));
                    const uint4 va = *reinterpret_cast<const uint4*>(Cb + oa);
                    acc_gene(acc, v0, n0);
                    v0 = va; n0 = na;
                    acc_gene(acc, v1, n1);
                    v1 = v0; n1 = n0;              // keep v1 as last
                    acc_gene(acc, v1, n1);
                } else {
                    acc_gene(acc, v0, n0);
                    acc_gene(acc, v1, n1);
                }
            } else {
                acc_gene(acc, v0, n0);
            }
        }

        *reinterpret_cast<float4*>(optr) = acc;
        optr += (size_t)NWARPS * N_SAMPLES;

        if (!more) break;
    }
}

extern "C" void kernel_launch(void* const* d_in, const int* in_sizes, int n_in,
                              void* d_out, int out_size)
{
    const float* A          = (const float*)d_in[0];
    const float* B          = (const float*)d_in[1];
    const float* pos        = (const float*)d_in[2];
    const int*   genome_idx = (const int*)d_in[3];
    const int*   seq_idx    = (const int*)d_in[4];
    float*       out        = (float*)d_out;

    prep_kernel<<<PREP_BLK, 256>>>(A, B, pos, genome_idx, seq_idx);
    seq_segsum_kernel<<<MAIN_BLOCKS, 256>>>(out);
}

// round 13
// speedup vs baseline: 1.1332x; 1.1332x over previous
#include <cuda_runtime.h>
#include <cuda_fp16.h>
#include <cstdint>

#define N_GENOMES 30000
#define N_GENES   240000
#define N_SAMPLES 128
#define N_SEQS    80000
#define CAP       32    // bucket capacity (Poisson(3): overflow prob ~1e-16)
#define FASTLANES 8     // slots read on the fast path; P(t>8) ~ 0.4% of seqs
#define LOG2E     1.4426950408889634f

#define GRID_BLOCKS 1480            // 10 CTAs/SM launched, 2 even resident waves
#define PREP_THREADS (GRID_BLOCKS * 256)
#define CONV_VEC  ((N_GENOMES * N_SAMPLES) / 4)   // 960000 uint4
#define CONV_HALF (CONV_VEC / 2)

// Scratch (device globals, zero-initialized at module load).
// d_C: per-genome interleaved fp16 (a_i,b_i) -> 512 B/row, 15.4 MB, L2-resident.
__device__ __half2 d_C[(size_t)N_GENOMES * N_SAMPLES];
__device__ int     d_count[N_SEQS];
__device__ int2    d_pairs[(size_t)N_SEQS * CAP];  // {row elem offset, bits(-pos*log2e)}

__device__ __forceinline__ float ex2f(float x) {
    float r; asm("ex2.approx.f32 %0, %1;" : "=f"(r) : "f"(x)); return r;
}
__device__ __forceinline__ uint32_t pack2(float a, float b) {
    __half2 h = __floats2half2_rn(a, b);
    return *reinterpret_cast<uint32_t*>(&h);
}

// Single-launch prep: phase 1 converts A,B into the interleaved fp16 table
// (2 uint4 per thread-iteration -> 4 independent loads in flight); phase 2
// buckets genes by sequence. Phases write disjoint data; no sync needed.
__global__ void __launch_bounds__(256) prep_kernel(
    const float* __restrict__ A,
    const float* __restrict__ B,
    const float* __restrict__ pos,
    const int*   __restrict__ genome_idx,
    const int*   __restrict__ seq_idx)
{
    const int tid = blockIdx.x * 256 + threadIdx.x;

    const float4* A4 = reinterpret_cast<const float4*>(A);
    const float4* B4 = reinterpret_cast<const float4*>(B);
    uint4* C4 = reinterpret_cast<uint4*>(d_C);

    for (int i = tid; i < CONV_HALF; i += PREP_THREADS) {
        const int j = i + CONV_HALF;
        const float4 a0 = __ldg(A4 + i);
        const float4 b0 = __ldg(B4 + i);
        const float4 a1 = __ldg(A4 + j);
        const float4 b1 = __ldg(B4 + j);
        uint4 o0, o1;
        o0.x = pack2(a0.x, b0.x); o0.y = pack2(a0.y, b0.y);
        o0.z = pack2(a0.z, b0.z); o0.w = pack2(a0.w, b0.w);
        o1.x = pack2(a1.x, b1.x); o1.y = pack2(a1.y, b1.y);
        o1.z = pack2(a1.z, b1.z); o1.w = pack2(a1.w, b1.w);
        C4[i] = o0;
        C4[j] = o1;
    }

    for (int g = tid; g < N_GENES; g += PREP_THREADS) {
        const int   s   = seq_idx[g];
        const int   off = genome_idx[g] * N_SAMPLES;
        const float np  = -pos[g] * LOG2E;
        const int slot = atomicAdd(&d_count[s], 1);
        if (slot < CAP)
            d_pairs[(size_t)s * CAP + slot] = make_int2(off, __float_as_int(np));
    }
}

// exp(A + 1 - p*B) = ex2( fma(B, -p*log2e, fma(A, log2e, log2e)) )
__device__ __forceinline__ void acc_gene(float4& acc, const uint4 v, const float np) {
    const float2 p0 = __half22float2(*reinterpret_cast<const __half2*>(&v.x));
    const float2 p1 = __half22float2(*reinterpret_cast<const __half2*>(&v.y));
    const float2 p2 = __half22float2(*reinterpret_cast<const __half2*>(&v.z));
    const float2 p3 = __half22float2(*reinterpret_cast<const __half2*>(&v.w));
    acc.x += ex2f(fmaf(p0.y, np, fmaf(p0.x, LOG2E, LOG2E)));
    acc.y += ex2f(fmaf(p1.y, np, fmaf(p1.x, LOG2E, LOG2E)));
    acc.z += ex2f(fmaf(p2.y, np, fmaf(p2.x, LOG2E, LOG2E)));
    acc.w += ex2f(fmaf(p3.y, np, fmaf(p3.x, LOG2E, LOG2E)));
}

// Main: persistent warp per seq. One LDG.128/lane per gene from the fp16
// table; depth-2 gene pipeline; next-seq metadata prefetch. Fast path reads
// only 8 bucket slots (64 B vs 256 B); rare t>8 reloads the full row.
// Resets d_count inline for the next graph replay.
__global__ void __launch_bounds__(256) seq_segsum_kernel(float* __restrict__ out)
{
    const int lane   = threadIdx.x & 31;
    const int nwarps = (gridDim.x * blockDim.x) >> 5;
    int seq = (blockIdx.x * blockDim.x + threadIdx.x) >> 5;
    if (seq >= N_SEQS) return;
    const int col = lane * 4;

    const char* __restrict__ Cb = reinterpret_cast<const char*>(d_C);

    int  tn  = __ldg(&d_count[seq]);
    int2 prn = make_int2(0, 0);
    if (lane < FASTLANES) prn = d_pairs[(size_t)seq * CAP + lane];

    while (true) {
        const int seq0 = seq;
        const int t    = min(tn, CAP);
        int2      pr   = prn;
        if (t > FASTLANES)                         // rare (~0.4%): full row
            pr = d_pairs[(size_t)seq0 * CAP + lane];
        if (lane == 0) d_count[seq0] = 0;          // reset for next replay

        seq += nwarps;
        const bool more = (seq < N_SEQS);
        if (more) {                                // prefetch next seq metadata
            tn = __ldg(&d_count[seq]);
            if (lane < FASTLANES) prn = d_pairs[(size_t)seq * CAP + lane];
        }

        float4 acc = make_float4(0.f, 0.f, 0.f, 0.f);
        if (t > 0) {
            size_t o0 = ((size_t)__shfl_sync(0xffffffffu, pr.x, 0) + col) * 4;
            float  n0 = __int_as_float(__shfl_sync(0xffffffffu, pr.y, 0));
            uint4  v0 = *reinterpret_cast<const uint4*>(Cb + o0);

            size_t o1 = ((size_t)__shfl_sync(0xffffffffu, pr.x, 1 % CAP) + col) * 4;
            float  n1 = __int_as_float(__shfl_sync(0xffffffffu, pr.y, 1 % CAP));
            uint4  v1 = (t > 1) ? *reinterpret_cast<const uint4*>(Cb + o1)
                                : make_uint4(0, 0, 0, 0);

            for (int k = 2; k < t; k++) {
                const size_t on = ((size_t)__shfl_sync(0xffffffffu, pr.x, k) + col) * 4;
                const float  nn = __int_as_float(__shfl_sync(0xffffffffu, pr.y, k));
                const uint4  vn = *reinterpret_cast<const uint4*>(Cb + on);
                acc_gene(acc, v0, n0);             // consume oldest; 2 in flight
                v0 = v1; n0 = n1;
                v1 = vn; n1 = nn;
            }
            acc_gene(acc, v0, n0);
            if (t > 1) acc_gene(acc, v1, n1);
        }

        *reinterpret_cast<float4*>(out + (size_t)seq0 * N_SAMPLES + col) = acc;

        if (!more) break;
    }
}

extern "C" void kernel_launch(void* const* d_in, const int* in_sizes, int n_in,
                              void* d_out, int out_size)
{
    const float* A          = (const float*)d_in[0];
    const float* B          = (const float*)d_in[1];
    const float* pos        = (const float*)d_in[2];
    const int*   genome_idx = (const int*)d_in[3];
    const int*   seq_idx    = (const int*)d_in[4];
    float*       out        = (float*)d_out;

    prep_kernel<<<GRID_BLOCKS, 256>>>(A, B, pos, genome_idx, seq_idx);
    seq_segsum_kernel<<<GRID_BLOCKS, 256>>>(out);
}

// round 14
// speedup vs baseline: 1.1877x; 1.0481x over previous
#include <cuda_runtime.h>
#include <cuda_fp16.h>
#include <cstdint>

#define N_GENOMES 30000
#define N_GENES   240000
#define N_SAMPLES 128
#define N_SEQS    80000
#define CAP       32    // bucket capacity (Poisson(3): overflow prob ~1e-16)
#define LOG2E     1.4426950408889634f
#define ROW_BYTES 512   // bytes per genome row in d_C (128 samples * 4 B)

#define GRID_BLOCKS 1480
#define PREP_THREADS (GRID_BLOCKS * 256)
#define CONV_VEC  ((N_GENOMES * N_SAMPLES) / 4)   // 960000 uint4
#define CONV_HALF (CONV_VEC / 2)

// Scratch (device globals, zero-initialized at module load).
// d_C: per-genome interleaved fp16 (a_i,b_i) -> 512 B/row, 15.4 MB, L2-resident.
__device__ __half2 d_C[(size_t)N_GENOMES * N_SAMPLES];
__device__ int     d_count[N_SEQS];
__device__ int2    d_pairs[(size_t)N_SEQS * CAP];  // {row BYTE offset, bits(-pos*log2e)}

__device__ __forceinline__ float ex2f(float x) {
    float r; asm("ex2.approx.f32 %0, %1;" : "=f"(r) : "f"(x)); return r;
}
__device__ __forceinline__ uint32_t pack2(float a, float b) {
    __half2 h = __floats2half2_rn(a, b);
    return *reinterpret_cast<uint32_t*>(&h);
}

// Single-launch prep: phase 1 converts A,B (streaming reads) into the fp16
// table; phase 2 buckets genes by sequence with premultiplied byte offsets.
__global__ void __launch_bounds__(256) prep_kernel(
    const float* __restrict__ A,
    const float* __restrict__ B,
    const float* __restrict__ pos,
    const int*   __restrict__ genome_idx,
    const int*   __restrict__ seq_idx)
{
    const int tid = blockIdx.x * 256 + threadIdx.x;

    const float4* A4 = reinterpret_cast<const float4*>(A);
    const float4* B4 = reinterpret_cast<const float4*>(B);
    uint4* C4 = reinterpret_cast<uint4*>(d_C);

    for (int i = tid; i < CONV_HALF; i += PREP_THREADS) {
        const int j = i + CONV_HALF;
        const float4 a0 = __ldcs(A4 + i);          // streaming: evict-first
        const float4 b0 = __ldcs(B4 + i);
        const float4 a1 = __ldcs(A4 + j);
        const float4 b1 = __ldcs(B4 + j);
        uint4 o0, o1;
        o0.x = pack2(a0.x, b0.x); o0.y = pack2(a0.y, b0.y);
        o0.z = pack2(a0.z, b0.z); o0.w = pack2(a0.w, b0.w);
        o1.x = pack2(a1.x, b1.x); o1.y = pack2(a1.y, b1.y);
        o1.z = pack2(a1.z, b1.z); o1.w = pack2(a1.w, b1.w);
        C4[i] = o0;                                // default policy: keep in L2
        C4[j] = o1;
    }

    for (int g = tid; g < N_GENES; g += PREP_THREADS) {
        const int   s   = seq_idx[g];
        const int   off = genome_idx[g] * ROW_BYTES;   // premultiplied bytes
        const float np  = -pos[g] * LOG2E;
        const int slot = atomicAdd(&d_count[s], 1);
        if (slot < CAP)
            d_pairs[(size_t)s * CAP + slot] = make_int2(off, __float_as_int(np));
    }
}

// exp(A + 1 - p*B) = ex2( fma(B, -p*log2e, fma(A, log2e, log2e)) )
__device__ __forceinline__ void acc_gene(float4& acc, const uint4 v, const float np) {
    const float2 p0 = __half22float2(*reinterpret_cast<const __half2*>(&v.x));
    const float2 p1 = __half22float2(*reinterpret_cast<const __half2*>(&v.y));
    const float2 p2 = __half22float2(*reinterpret_cast<const __half2*>(&v.z));
    const float2 p3 = __half22float2(*reinterpret_cast<const __half2*>(&v.w));
    acc.x += ex2f(fmaf(p0.y, np, fmaf(p0.x, LOG2E, LOG2E)));
    acc.y += ex2f(fmaf(p1.y, np, fmaf(p1.x, LOG2E, LOG2E)));
    acc.z += ex2f(fmaf(p2.y, np, fmaf(p2.x, LOG2E, LOG2E)));
    acc.w += ex2f(fmaf(p3.y, np, fmaf(p3.x, LOG2E, LOG2E)));
}

// Main: persistent warp per seq. One LDG.128/lane per gene from the
// L2-resident fp16 table; depth-2 gene pipeline; next-seq metadata prefetch.
// Addresses are single 32-bit adds (offsets premultiplied at scatter).
// Resets d_count inline for the next graph replay. Output stored streaming.
__global__ void __launch_bounds__(256) seq_segsum_kernel(float* __restrict__ out)
{
    const int lane   = threadIdx.x & 31;
    const int nwarps = (gridDim.x * blockDim.x) >> 5;
    int seq = (blockIdx.x * blockDim.x + threadIdx.x) >> 5;
    if (seq >= N_SEQS) return;

    const char* __restrict__ Cb = reinterpret_cast<const char*>(d_C) + lane * 16;

    int  tn  = __ldg(&d_count[seq]);
    int2 prn = __ldcs(&d_pairs[(size_t)seq * CAP + lane]);

    while (true) {
        const int  seq0 = seq;
        const int  t    = min(tn, CAP);
        const int2 pr   = prn;
        if (lane == 0) d_count[seq0] = 0;          // reset for next replay

        seq += nwarps;
        const bool more = (seq < N_SEQS);
        if (more) {                                // prefetch next seq metadata
            tn  = __ldg(&d_count[seq]);
            prn = __ldcs(&d_pairs[(size_t)seq * CAP + lane]);
        }

        float4 acc = make_float4(0.f, 0.f, 0.f, 0.f);
        if (t > 0) {
            uint32_t o0 = __shfl_sync(0xffffffffu, pr.x, 0);
            float    n0 = __int_as_float(__shfl_sync(0xffffffffu, pr.y, 0));
            uint4    v0 = *reinterpret_cast<const uint4*>(Cb + o0);

            uint32_t o1 = __shfl_sync(0xffffffffu, pr.x, 1 % CAP);
            float    n1 = __int_as_float(__shfl_sync(0xffffffffu, pr.y, 1 % CAP));
            uint4    v1 = (t > 1) ? *reinterpret_cast<const uint4*>(Cb + o1)
                                  : make_uint4(0, 0, 0, 0);

            for (int k = 2; k < t; k++) {
                const uint32_t on = __shfl_sync(0xffffffffu, pr.x, k);
                const float    nn = __int_as_float(__shfl_sync(0xffffffffu, pr.y, k));
                const uint4    vn = *reinterpret_cast<const uint4*>(Cb + on);
                acc_gene(acc, v0, n0);             // consume oldest; 2 in flight
                v0 = v1; n0 = n1;
                v1 = vn; n1 = nn;
            }
            acc_gene(acc, v0, n0);
            if (t > 1) acc_gene(acc, v1, n1);
        }

        // Streaming store: written once, never re-read -> don't pollute L2.
        __stcs(reinterpret_cast<float4*>(out + (size_t)seq0 * N_SAMPLES + lane * 4), acc);

        if (!more) break;
    }
}

extern "C" void kernel_launch(void* const* d_in, const int* in_sizes, int n_in,
                              void* d_out, int out_size)
{
    const float* A          = (const float*)d_in[0];
    const float* B          = (const float*)d_in[1];
    const float* pos        = (const float*)d_in[2];
    const int*   genome_idx = (const int*)d_in[3];
    const int*   seq_idx    = (const int*)d_in[4];
    float*       out        = (float*)d_out;

    prep_kernel<<<GRID_BLOCKS, 256>>>(A, B, pos, genome_idx, seq_idx);
    seq_segsum_kernel<<<GRID_BLOCKS, 256>>>(out);
}